// round 8
// baseline (speedup 1.0000x reference)
#include <cuda_runtime.h>
#include <cuda_bf16.h>
#include <cstdint>

// SwinStyleAttention, mma.sync bf16 hi/lo 3-pass. R8: R7 with MMA issue reordered
// pass-major so consecutive MMAs never share an accumulator (D-RAW distance 8/4/8
// in gemm/QK/PV instead of 1-2). Everything else identical to R7.

#define SCALE_ 0.17677669529663687f
#define SWZ(row, colb) (((row) << 8) + ((colb) ^ (((row) & 7) << 4)))

#define XHI   0
#define XLO   16384
#define KHPL  32768
#define KLPL  49152
#define VHPL  65536
#define VLPL  81920
#define PW(i) (98304 + (i) * 32768)
#define BIASO 229376
#define SMEM_BYTES 229888

__device__ __nv_bfloat16 g_wq[3][2][16384];
__device__ __nv_bfloat16 g_wp[2][16384];

static __device__ __forceinline__ uint32_t smem_u32(const void* p) {
    uint32_t a;
    asm("{ .reg .u64 t; cvta.to.shared.u64 t, %1; cvt.u32.u64 %0, t; }" : "=r"(a) : "l"(p));
    return a;
}

#define LDSM4(R0, R1, R2, R3, ADDR) \
    asm volatile("ldmatrix.sync.aligned.m8n8.x4.shared.b16 {%0,%1,%2,%3}, [%4];" \
                 : "=r"(R0), "=r"(R1), "=r"(R2), "=r"(R3) : "r"(ADDR))
#define LDSM4T(R0, R1, R2, R3, ADDR) \
    asm volatile("ldmatrix.sync.aligned.m8n8.x4.trans.shared.b16 {%0,%1,%2,%3}, [%4];" \
                 : "=r"(R0), "=r"(R1), "=r"(R2), "=r"(R3) : "r"(ADDR))
#define MMA(D, A, B) \
    asm volatile("mma.sync.aligned.m16n8k16.row.col.f32.bf16.bf16.f32 " \
                 "{%0,%1,%2,%3},{%4,%5,%6,%7},{%8,%9},{%0,%1,%2,%3};" \
                 : "+f"((D)[0]), "+f"((D)[1]), "+f"((D)[2]), "+f"((D)[3]) \
                 : "r"((A)[0]), "r"((A)[1]), "r"((A)[2]), "r"((A)[3]), \
                   "r"((B)[0]), "r"((B)[1]))
#define CP_ASYNC16(DST, SRC) \
    asm volatile("cp.async.cg.shared.global [%0], [%1], 16;" :: "r"(DST), "l"(SRC))
#define CP_COMMIT() asm volatile("cp.async.commit_group;")
#define CP_WAIT0()  asm volatile("cp.async.wait_group 0;")

static __device__ __forceinline__ void split2(float x, float y, uint32_t& hi, uint32_t& lo) {
    __nv_bfloat16 hx = __float2bfloat16(x), hy = __float2bfloat16(y);
    __nv_bfloat16 lx = __float2bfloat16(x - __bfloat162float(hx));
    __nv_bfloat16 ly = __float2bfloat16(y - __bfloat162float(hy));
    hi = (uint32_t)__bfloat16_as_ushort(hx) | ((uint32_t)__bfloat16_as_ushort(hy) << 16);
    lo = (uint32_t)__bfloat16_as_ushort(lx) | ((uint32_t)__bfloat16_as_ushort(ly) << 16);
}

// ---------------- prep: transpose + hi/lo split weights into swizzled planes --------------
__global__ void prep_weights(const float* __restrict__ wqkv, const float* __restrict__ wproj) {
    int i = blockIdx.x * blockDim.x + threadIdx.x;
    if (i < 49152) {
        int k = i & 127, n = (i >> 7) & 127, nc = i >> 14;
        float v = wqkv[k * 384 + nc * 128 + n];
        __nv_bfloat16 h = __float2bfloat16(v);
        int off = n * 128 + (k ^ ((n & 7) << 3));
        g_wq[nc][0][off] = h;
        g_wq[nc][1][off] = __float2bfloat16(v - __bfloat162float(h));
    } else if (i < 65536) {
        int j = i - 49152;
        int k = j & 127, n = (j >> 7) & 127;
        float v = wproj[k * 128 + n];
        __nv_bfloat16 h = __float2bfloat16(v);
        int off = n * 128 + (k ^ ((n & 7) << 3));
        g_wp[0][off] = h;
        g_wp[1][off] = __float2bfloat16(v - __bfloat162float(h));
    }
}

// ---------------- main fused kernel ----------------
__global__ __launch_bounds__(256, 1)
void swin_mma6_kernel(const float* __restrict__ x,
                      const float* __restrict__ b_proj,
                      float* __restrict__ out)
{
    extern __shared__ __align__(256) unsigned char smem[];
    const uint32_t sb = smem_u32(smem);

    const int tid = threadIdx.x;
    const int lane = tid & 31;
    const int warp = tid >> 5;     // 0..7
    const int g = lane >> 2;
    const int t4 = lane & 3;

    const int win = blockIdx.x;
    const int b = win >> 10, wy = (win >> 5) & 31, wx = win & 31;
    const int hbase = wy * 8 + 4, wbase = wx * 8 + 4;

    auto cpplane = [&](uint32_t dstPlane, const __nv_bfloat16* src) {
        const char* s = (const char*)src;
        #pragma unroll
        for (int i = 0; i < 8; i++) {
            int off = (tid + i * 256) * 16;
            CP_ASYNC16(sb + dstPlane + off, s + off);
        }
        CP_COMMIT();
    };

    cpplane(PW(0), g_wq[0][0]);
    cpplane(PW(1), g_wq[0][1]);
    cpplane(PW(2), g_wq[1][0]);
    cpplane(PW(3), g_wq[1][1]);

    // ---- phase 0: bias + rolled-window gather ----
    if (tid < 128) ((float*)(smem + BIASO))[tid] = b_proj[tid];
    #pragma unroll
    for (int it = 0; it < 4; it++) {
        int idx = tid + it * 256;
        int t = idx & 63, cq = idx >> 6;
        int h = (hbase + (t >> 3)) & 255;
        int w = (wbase + (t & 7)) & 255;
        const float* xg = x + (size_t)(b * 128 + cq * 8) * 65536 + h * 256 + w;
        uint32_t hp[4], lp[4];
        #pragma unroll
        for (int j = 0; j < 4; j++) {
            float f0 = xg[(size_t)(2 * j) << 16];
            float f1 = xg[(size_t)(2 * j + 1) << 16];
            split2(f0, f1, hp[j], lp[j]);
        }
        *(uint4*)(smem + XHI + SWZ(t, cq * 16)) = make_uint4(hp[0], hp[1], hp[2], hp[3]);
        *(uint4*)(smem + XLO + SWZ(t, cq * 16)) = make_uint4(lp[0], lp[1], lp[2], lp[3]);
    }
    CP_WAIT0();
    __syncthreads();

    const int mbase = (warp >> 2) * 32;
    const int nbase = (warp & 3) * 32;

    float acc[2][4][4];
    // 32x32-tile GEMM, double-buffered loads + pass-major MMA order (acc distance 8)
    auto gemm = [&](uint32_t whi, uint32_t wlo) {
        #pragma unroll
        for (int mf = 0; mf < 2; mf++)
            #pragma unroll
            for (int nt = 0; nt < 4; nt++)
                #pragma unroll
                for (int q = 0; q < 4; q++) acc[mf][nt][q] = 0.f;
        const int arow = mbase + (lane & 15);
        const int brow = nbase + ((lane >> 4) << 3) + (lane & 7);
        uint32_t ah[2][2][4], al[2][2][4], bh[2][4][2], bl[2][4][2];
        auto loadk = [&](int kt, int st) {
            const int acolb = kt * 32 + (lane >> 4) * 16;
            const int bcolb = kt * 32 + ((lane >> 3) & 1) * 16;
            #pragma unroll
            for (int mf = 0; mf < 2; mf++) {
                LDSM4(ah[st][mf][0], ah[st][mf][1], ah[st][mf][2], ah[st][mf][3],
                      sb + XHI + SWZ(arow + mf * 16, acolb));
                LDSM4(al[st][mf][0], al[st][mf][1], al[st][mf][2], al[st][mf][3],
                      sb + XLO + SWZ(arow + mf * 16, acolb));
            }
            #pragma unroll
            for (int ng = 0; ng < 2; ng++) {
                uint32_t r0, r1, r2, r3;
                LDSM4(r0, r1, r2, r3, sb + whi + SWZ(brow + ng * 16, bcolb));
                bh[st][2 * ng][0] = r0; bh[st][2 * ng][1] = r1;
                bh[st][2 * ng + 1][0] = r2; bh[st][2 * ng + 1][1] = r3;
                LDSM4(r0, r1, r2, r3, sb + wlo + SWZ(brow + ng * 16, bcolb));
                bl[st][2 * ng][0] = r0; bl[st][2 * ng][1] = r1;
                bl[st][2 * ng + 1][0] = r2; bl[st][2 * ng + 1][1] = r3;
            }
        };
        loadk(0, 0);
        #pragma unroll
        for (int kt = 0; kt < 8; kt++) {
            const int cur = kt & 1;
            if (kt < 7) loadk(kt + 1, cur ^ 1);
            // pass-major: same-acc MMAs are 8 apart
            #pragma unroll
            for (int mf = 0; mf < 2; mf++)
                #pragma unroll
                for (int nt = 0; nt < 4; nt++)
                    MMA(acc[mf][nt], ah[cur][mf], bh[cur][nt]);
            #pragma unroll
            for (int mf = 0; mf < 2; mf++)
                #pragma unroll
                for (int nt = 0; nt < 4; nt++)
                    MMA(acc[mf][nt], ah[cur][mf], bl[cur][nt]);
            #pragma unroll
            for (int mf = 0; mf < 2; mf++)
                #pragma unroll
                for (int nt = 0; nt < 4; nt++)
                    MMA(acc[mf][nt], al[cur][mf], bh[cur][nt]);
        }
    };
    auto store_y = [&](uint32_t yh, uint32_t yl) {
        #pragma unroll
        for (int mf = 0; mf < 2; mf++)
            #pragma unroll
            for (int nt = 0; nt < 4; nt++) {
                int ch = nbase + nt * 8 + 2 * t4;
                int tok = mbase + mf * 16 + g;
                uint32_t hi, lo;
                split2(acc[mf][nt][0], acc[mf][nt][1], hi, lo);
                *(uint32_t*)(smem + yh + SWZ(tok, ch * 2)) = hi;
                *(uint32_t*)(smem + yl + SWZ(tok, ch * 2)) = lo;
                split2(acc[mf][nt][2], acc[mf][nt][3], hi, lo);
                *(uint32_t*)(smem + yh + SWZ(tok + 8, ch * 2)) = hi;
                *(uint32_t*)(smem + yl + SWZ(tok + 8, ch * 2)) = lo;
            }
    };

    // ---- phase 1a: q chunk -> registers only ----
    gemm(PW(0), PW(1));
    uint32_t qfh[2][2][4], qfl[2][2][4];
    #pragma unroll
    for (int mf = 0; mf < 2; mf++)
        #pragma unroll
        for (int kt = 0; kt < 2; kt++) {
            split2(acc[mf][2*kt][0] * SCALE_, acc[mf][2*kt][1] * SCALE_, qfh[mf][kt][0], qfl[mf][kt][0]);
            split2(acc[mf][2*kt][2] * SCALE_, acc[mf][2*kt][3] * SCALE_, qfh[mf][kt][1], qfl[mf][kt][1]);
            split2(acc[mf][2*kt+1][0] * SCALE_, acc[mf][2*kt+1][1] * SCALE_, qfh[mf][kt][2], qfl[mf][kt][2]);
            split2(acc[mf][2*kt+1][2] * SCALE_, acc[mf][2*kt+1][3] * SCALE_, qfh[mf][kt][3], qfl[mf][kt][3]);
        }
    __syncthreads();

    // ---- phase 1b: k chunk ----
    cpplane(PW(0), g_wq[2][0]);
    cpplane(PW(1), g_wq[2][1]);
    gemm(PW(2), PW(3));
    store_y(KHPL, KLPL);
    CP_WAIT0();
    __syncthreads();

    // ---- phase 1c: v chunk ----
    gemm(PW(0), PW(1));
    store_y(VHPL, VLPL);
    __syncthreads();

    cpplane(PW(2), g_wp[0]);
    cpplane(PW(3), g_wp[1]);

    // ---- phase 2: attention ----
    {
        const int chB = (warp & 3) * 64;

        float s[2][8][4];
        #pragma unroll
        for (int mf = 0; mf < 2; mf++)
            #pragma unroll
            for (int j = 0; j < 8; j++)
                #pragma unroll
                for (int q = 0; q < 4; q++) s[mf][j][q] = 0.f;

        // QK^T pipelined; per-it pass-major across mf and fragment -> acc distance 4
        {
            uint32_t kh[2][4], kl[2][4];
            auto loadK = [&](int it, int st) {
                const int kt = it >> 2, ng = it & 3;
                const int bcolb = chB + kt * 32 + ((lane >> 3) & 1) * 16;
                const int brow = ng * 16 + ((lane >> 4) << 3) + (lane & 7);
                LDSM4(kh[st][0], kh[st][1], kh[st][2], kh[st][3], sb + KHPL + SWZ(brow, bcolb));
                LDSM4(kl[st][0], kl[st][1], kl[st][2], kl[st][3], sb + KLPL + SWZ(brow, bcolb));
            };
            loadK(0, 0);
            #pragma unroll
            for (int it = 0; it < 8; it++) {
                const int cur = it & 1;
                if (it < 7) loadK(it + 1, cur ^ 1);
                const int kt = it >> 2, ng = it & 3;
                // pass 1 (qh x kh): 4 distinct accumulators
                #pragma unroll
                for (int mf = 0; mf < 2; mf++) {
                    MMA(s[mf][2*ng],   qfh[mf][kt], kh[cur]);
                    MMA(s[mf][2*ng+1], qfh[mf][kt], kh[cur] + 2);
                }
                // pass 2 (qh x kl)
                #pragma unroll
                for (int mf = 0; mf < 2; mf++) {
                    MMA(s[mf][2*ng],   qfh[mf][kt], kl[cur]);
                    MMA(s[mf][2*ng+1], qfh[mf][kt], kl[cur] + 2);
                }
                // pass 3 (ql x kh)
                #pragma unroll
                for (int mf = 0; mf < 2; mf++) {
                    MMA(s[mf][2*ng],   qfl[mf][kt], kh[cur]);
                    MMA(s[mf][2*ng+1], qfl[mf][kt], kh[cur] + 2);
                }
            }
        }
        // softmax
        float inv0[2], inv1[2];
        #pragma unroll
        for (int mf = 0; mf < 2; mf++) {
            float mx0 = -1e30f, mx1 = -1e30f;
            #pragma unroll
            for (int j = 0; j < 8; j++) {
                mx0 = fmaxf(mx0, fmaxf(s[mf][j][0], s[mf][j][1]));
                mx1 = fmaxf(mx1, fmaxf(s[mf][j][2], s[mf][j][3]));
            }
            mx0 = fmaxf(mx0, __shfl_xor_sync(0xffffffffu, mx0, 1));
            mx0 = fmaxf(mx0, __shfl_xor_sync(0xffffffffu, mx0, 2));
            mx1 = fmaxf(mx1, __shfl_xor_sync(0xffffffffu, mx1, 1));
            mx1 = fmaxf(mx1, __shfl_xor_sync(0xffffffffu, mx1, 2));
            float sm0 = 0.f, sm1 = 0.f;
            #pragma unroll
            for (int j = 0; j < 8; j++) {
                s[mf][j][0] = __expf(s[mf][j][0] - mx0); sm0 += s[mf][j][0];
                s[mf][j][1] = __expf(s[mf][j][1] - mx0); sm0 += s[mf][j][1];
                s[mf][j][2] = __expf(s[mf][j][2] - mx1); sm1 += s[mf][j][2];
                s[mf][j][3] = __expf(s[mf][j][3] - mx1); sm1 += s[mf][j][3];
            }
            sm0 += __shfl_xor_sync(0xffffffffu, sm0, 1);
            sm0 += __shfl_xor_sync(0xffffffffu, sm0, 2);
            sm1 += __shfl_xor_sync(0xffffffffu, sm1, 1);
            sm1 += __shfl_xor_sync(0xffffffffu, sm1, 2);
            inv0[mf] = 1.f / sm0; inv1[mf] = 1.f / sm1;
        }

        // P @ V: hoist P frags for both mf per kt, pass-major MMAs (acc distance 8)
        float o[2][4][4];
        #pragma unroll
        for (int mf = 0; mf < 2; mf++)
            #pragma unroll
            for (int nt = 0; nt < 4; nt++)
                #pragma unroll
                for (int q = 0; q < 4; q++) o[mf][nt][q] = 0.f;
        {
            uint32_t vh[2][4][2], vl[2][4][2];
            auto loadV = [&](int kt, int st) {
                const int vrow = kt * 16 + (lane & 15);
                #pragma unroll
                for (int ng = 0; ng < 2; ng++) {
                    const int vcolb = chB + ng * 32 + (lane >> 4) * 16;
                    uint32_t r0, r1, r2, r3;
                    LDSM4T(r0, r1, r2, r3, sb + VHPL + SWZ(vrow, vcolb));
                    vh[st][2 * ng][0] = r0; vh[st][2 * ng][1] = r1;
                    vh[st][2 * ng + 1][0] = r2; vh[st][2 * ng + 1][1] = r3;
                    LDSM4T(r0, r1, r2, r3, sb + VLPL + SWZ(vrow, vcolb));
                    vl[st][2 * ng][0] = r0; vl[st][2 * ng][1] = r1;
                    vl[st][2 * ng + 1][0] = r2; vl[st][2 * ng + 1][1] = r3;
                }
            };
            loadV(0, 0);
            #pragma unroll
            for (int kt = 0; kt < 4; kt++) {
                const int cur = kt & 1;
                if (kt < 3) loadV(kt + 1, cur ^ 1);
                uint32_t pah[2][4], pal[2][4];
                #pragma unroll
                for (int mf = 0; mf < 2; mf++) {
                    split2(s[mf][2*kt][0] * inv0[mf], s[mf][2*kt][1] * inv0[mf], pah[mf][0], pal[mf][0]);
                    split2(s[mf][2*kt][2] * inv1[mf], s[mf][2*kt][3] * inv1[mf], pah[mf][1], pal[mf][1]);
                    split2(s[mf][2*kt+1][0] * inv0[mf], s[mf][2*kt+1][1] * inv0[mf], pah[mf][2], pal[mf][2]);
                    split2(s[mf][2*kt+1][2] * inv1[mf], s[mf][2*kt+1][3] * inv1[mf], pah[mf][3], pal[mf][3]);
                }
                #pragma unroll
                for (int mf = 0; mf < 2; mf++)
                    #pragma unroll
                    for (int nt = 0; nt < 4; nt++)
                        MMA(o[mf][nt], pah[mf], vh[cur][nt]);
                #pragma unroll
                for (int mf = 0; mf < 2; mf++)
                    #pragma unroll
                    for (int nt = 0; nt < 4; nt++)
                        MMA(o[mf][nt], pah[mf], vl[cur][nt]);
                #pragma unroll
                for (int mf = 0; mf < 2; mf++)
                    #pragma unroll
                    for (int nt = 0; nt < 4; nt++)
                        MMA(o[mf][nt], pal[mf], vh[cur][nt]);
            }
        }
        // store O (hi/lo) into X planes
        #pragma unroll
        for (int mf = 0; mf < 2; mf++)
            #pragma unroll
            for (int nt = 0; nt < 4; nt++) {
                int ch = (warp & 3) * 32 + nt * 8 + 2 * t4;
                int tok = (warp >> 2) * 32 + mf * 16 + g;
                uint32_t hi, lo;
                split2(o[mf][nt][0], o[mf][nt][1], hi, lo);
                *(uint32_t*)(smem + XHI + SWZ(tok, ch * 2)) = hi;
                *(uint32_t*)(smem + XLO + SWZ(tok, ch * 2)) = lo;
                split2(o[mf][nt][2], o[mf][nt][3], hi, lo);
                *(uint32_t*)(smem + XHI + SWZ(tok + 8, ch * 2)) = hi;
                *(uint32_t*)(smem + XLO + SWZ(tok + 8, ch * 2)) = lo;
            }
    }
    CP_WAIT0();
    __syncthreads();

    // ---- phase 3: proj = O @ Wproj + bias; direct global scatter ----
    gemm(PW(2), PW(3));
    {
        const float* bias = (const float*)(smem + BIASO);
        #pragma unroll
        for (int mf = 0; mf < 2; mf++) {
            const int tok0 = mbase + mf * 16 + g;
            const int tok1 = tok0 + 8;
            const int h0 = (hbase + (tok0 >> 3)) & 255, w0 = (wbase + (tok0 & 7)) & 255;
            const int h1 = (hbase + (tok1 >> 3)) & 255, w1 = (wbase + (tok1 & 7)) & 255;
            const size_t p0 = (size_t)h0 * 256 + w0;
            const size_t p1 = (size_t)h1 * 256 + w1;
            #pragma unroll
            for (int nt = 0; nt < 4; nt++) {
                const int c0 = nbase + nt * 8 + 2 * t4, c1 = c0 + 1;
                float* o0 = out + (size_t)(b * 128 + c0) * 65536;
                float* o1 = out + (size_t)(b * 128 + c1) * 65536;
                o0[p0] = acc[mf][nt][0] + bias[c0];
                o1[p0] = acc[mf][nt][1] + bias[c1];
                o0[p1] = acc[mf][nt][2] + bias[c0];
                o1[p1] = acc[mf][nt][3] + bias[c1];
            }
        }
    }
}

extern "C" void kernel_launch(void* const* d_in, const int* in_sizes, int n_in,
                              void* d_out, int out_size)
{
    const float* x      = (const float*)d_in[0];
    const float* w_qkv  = (const float*)d_in[1];
    const float* w_proj = (const float*)d_in[2];
    const float* b_proj = (const float*)d_in[3];
    float* out = (float*)d_out;

    prep_weights<<<256, 256>>>(w_qkv, w_proj);

    cudaFuncSetAttribute(swin_mma6_kernel,
                         cudaFuncAttributeMaxDynamicSharedMemorySize, SMEM_BYTES);
    swin_mma6_kernel<<<8192, 256, SMEM_BYTES>>>(x, b_proj, out);
}

// round 11
// speedup vs baseline: 1.0023x; 1.0023x over previous
#include <cuda_runtime.h>
#include <cuda_bf16.h>
#include <cstdint>

// SwinStyleAttention, mma.sync bf16 hi/lo 3-pass. R9: all 6 qkv W planes prefetched
// at entry; K/V planes REUSE spent W planes (same 229888B smem); q->k gemm with
// arrive-barrier only; attention split per-mf for register relief. 4 full barriers.

#define SCALE_ 0.17677669529663687f
#define SWZ(row, colb) (((row) << 8) + ((colb) ^ (((row) & 7) << 4)))

#define PW(i) ((i) * 32768)            // 6 weight planes: 0..196607
#define XHI   196608
#define XLO   212992
#define BIASO 229376
#define SMEM_BYTES 229888
// plane reuse after gemms:
#define KH2 PW(0)
#define KL2 PW(1)
#define VH2 PW(2)
#define VL2 PW(3)

__device__ __nv_bfloat16 g_wq[3][2][16384];
__device__ __nv_bfloat16 g_wp[2][16384];

static __device__ __forceinline__ uint32_t smem_u32(const void* p) {
    uint32_t a;
    asm("{ .reg .u64 t; cvta.to.shared.u64 t, %1; cvt.u32.u64 %0, t; }" : "=r"(a) : "l"(p));
    return a;
}

#define LDSM4(R0, R1, R2, R3, ADDR) \
    asm volatile("ldmatrix.sync.aligned.m8n8.x4.shared.b16 {%0,%1,%2,%3}, [%4];" \
                 : "=r"(R0), "=r"(R1), "=r"(R2), "=r"(R3) : "r"(ADDR))
#define LDSM4T(R0, R1, R2, R3, ADDR) \
    asm volatile("ldmatrix.sync.aligned.m8n8.x4.trans.shared.b16 {%0,%1,%2,%3}, [%4];" \
                 : "=r"(R0), "=r"(R1), "=r"(R2), "=r"(R3) : "r"(ADDR))
#define MMA(D, A, B) \
    asm volatile("mma.sync.aligned.m16n8k16.row.col.f32.bf16.bf16.f32 " \
                 "{%0,%1,%2,%3},{%4,%5,%6,%7},{%8,%9},{%0,%1,%2,%3};" \
                 : "+f"((D)[0]), "+f"((D)[1]), "+f"((D)[2]), "+f"((D)[3]) \
                 : "r"((A)[0]), "r"((A)[1]), "r"((A)[2]), "r"((A)[3]), \
                   "r"((B)[0]), "r"((B)[1]))
#define CP_ASYNC16(DST, SRC) \
    asm volatile("cp.async.cg.shared.global [%0], [%1], 16;" :: "r"(DST), "l"(SRC))
#define CP_COMMIT()   asm volatile("cp.async.commit_group;")
#define CP_WAITG(n)   asm volatile("cp.async.wait_group %0;" :: "n"(n))
#define BAR_ARRIVE()  asm volatile("bar.arrive 1, 512;" ::: "memory")
#define BAR_SYNC()    asm volatile("bar.sync 1, 512;" ::: "memory")

static __device__ __forceinline__ void split2(float x, float y, uint32_t& hi, uint32_t& lo) {
    __nv_bfloat16 hx = __float2bfloat16(x), hy = __float2bfloat16(y);
    __nv_bfloat16 lx = __float2bfloat16(x - __bfloat162float(hx));
    __nv_bfloat16 ly = __float2bfloat16(y - __bfloat162float(hy));
    hi = (uint32_t)__bfloat16_as_ushort(hx) | ((uint32_t)__bfloat16_as_ushort(hy) << 16);
    lo = (uint32_t)__bfloat16_as_ushort(lx) | ((uint32_t)__bfloat16_as_ushort(ly) << 16);
}

// ---------------- prep: transpose + hi/lo split weights into swizzled planes --------------
__global__ void prep_weights(const float* __restrict__ wqkv, const float* __restrict__ wproj) {
    int i = blockIdx.x * blockDim.x + threadIdx.x;
    if (i < 49152) {
        int k = i & 127, n = (i >> 7) & 127, nc = i >> 14;
        float v = wqkv[k * 384 + nc * 128 + n];
        __nv_bfloat16 h = __float2bfloat16(v);
        int off = n * 128 + (k ^ ((n & 7) << 3));
        g_wq[nc][0][off] = h;
        g_wq[nc][1][off] = __float2bfloat16(v - __bfloat162float(h));
    } else if (i < 65536) {
        int j = i - 49152;
        int k = j & 127, n = (j >> 7) & 127;
        float v = wproj[k * 128 + n];
        __nv_bfloat16 h = __float2bfloat16(v);
        int off = n * 128 + (k ^ ((n & 7) << 3));
        g_wp[0][off] = h;
        g_wp[1][off] = __float2bfloat16(v - __bfloat162float(h));
    }
}

// ---------------- main fused kernel ----------------
__global__ __launch_bounds__(256, 1)
void swin_mma7_kernel(const float* __restrict__ x,
                      const float* __restrict__ b_proj,
                      float* __restrict__ out)
{
    extern __shared__ __align__(256) unsigned char smem[];
    const uint32_t sb = smem_u32(smem);

    const int tid = threadIdx.x;
    const int lane = tid & 31;
    const int warp = tid >> 5;     // 0..7
    const int g = lane >> 2;
    const int t4 = lane & 3;

    const int win = blockIdx.x;
    const int b = win >> 10, wy = (win >> 5) & 31, wx = win & 31;
    const int hbase = wy * 8 + 4, wbase = wx * 8 + 4;

    auto cpplane = [&](uint32_t dstPlane, const __nv_bfloat16* src) {
        const char* s = (const char*)src;
        #pragma unroll
        for (int i = 0; i < 8; i++) {
            int off = (tid + i * 256) * 16;
            CP_ASYNC16(sb + dstPlane + off, s + off);
        }
        CP_COMMIT();
    };

    // prefetch ALL qkv weight planes up front (6 groups, issue order q,k,v)
    cpplane(PW(0), g_wq[0][0]);
    cpplane(PW(1), g_wq[0][1]);
    cpplane(PW(2), g_wq[1][0]);
    cpplane(PW(3), g_wq[1][1]);
    cpplane(PW(4), g_wq[2][0]);
    cpplane(PW(5), g_wq[2][1]);

    // ---- phase 0: bias + rolled-window gather into X hi/lo planes ----
    if (tid < 128) ((float*)(smem + BIASO))[tid] = b_proj[tid];
    #pragma unroll
    for (int it = 0; it < 4; it++) {
        int idx = tid + it * 256;
        int t = idx & 63, cq = idx >> 6;
        int h = (hbase + (t >> 3)) & 255;
        int w = (wbase + (t & 7)) & 255;
        const float* xg = x + (size_t)(b * 128 + cq * 8) * 65536 + h * 256 + w;
        uint32_t hp[4], lp[4];
        #pragma unroll
        for (int j = 0; j < 4; j++) {
            float f0 = xg[(size_t)(2 * j) << 16];
            float f1 = xg[(size_t)(2 * j + 1) << 16];
            split2(f0, f1, hp[j], lp[j]);
        }
        *(uint4*)(smem + XHI + SWZ(t, cq * 16)) = make_uint4(hp[0], hp[1], hp[2], hp[3]);
        *(uint4*)(smem + XLO + SWZ(t, cq * 16)) = make_uint4(lp[0], lp[1], lp[2], lp[3]);
    }
    CP_WAITG(2);          // q + k planes landed (first 4 of 6 groups)
    __syncthreads();      // S1: X + Wq + Wk visible

    const int mbase = (warp >> 2) * 32;
    const int nbase = (warp & 3) * 32;

    float acc[2][4][4];
    auto gemm = [&](uint32_t whi, uint32_t wlo) {
        #pragma unroll
        for (int mf = 0; mf < 2; mf++)
            #pragma unroll
            for (int nt = 0; nt < 4; nt++)
                #pragma unroll
                for (int q = 0; q < 4; q++) acc[mf][nt][q] = 0.f;
        const int arow = mbase + (lane & 15);
        const int brow = nbase + ((lane >> 4) << 3) + (lane & 7);
        uint32_t ah[2][2][4], al[2][2][4], bh[2][4][2], bl[2][4][2];
        auto loadk = [&](int kt, int st) {
            const int acolb = kt * 32 + (lane >> 4) * 16;
            const int bcolb = kt * 32 + ((lane >> 3) & 1) * 16;
            #pragma unroll
            for (int mf = 0; mf < 2; mf++) {
                LDSM4(ah[st][mf][0], ah[st][mf][1], ah[st][mf][2], ah[st][mf][3],
                      sb + XHI + SWZ(arow + mf * 16, acolb));
                LDSM4(al[st][mf][0], al[st][mf][1], al[st][mf][2], al[st][mf][3],
                      sb + XLO + SWZ(arow + mf * 16, acolb));
            }
            #pragma unroll
            for (int ng = 0; ng < 2; ng++) {
                uint32_t r0, r1, r2, r3;
                LDSM4(r0, r1, r2, r3, sb + whi + SWZ(brow + ng * 16, bcolb));
                bh[st][2 * ng][0] = r0; bh[st][2 * ng][1] = r1;
                bh[st][2 * ng + 1][0] = r2; bh[st][2 * ng + 1][1] = r3;
                LDSM4(r0, r1, r2, r3, sb + wlo + SWZ(brow + ng * 16, bcolb));
                bl[st][2 * ng][0] = r0; bl[st][2 * ng][1] = r1;
                bl[st][2 * ng + 1][0] = r2; bl[st][2 * ng + 1][1] = r3;
            }
        };
        loadk(0, 0);
        #pragma unroll
        for (int kt = 0; kt < 8; kt++) {
            const int cur = kt & 1;
            if (kt < 7) loadk(kt + 1, cur ^ 1);
            #pragma unroll
            for (int mf = 0; mf < 2; mf++)
                #pragma unroll
                for (int nt = 0; nt < 4; nt++)
                    MMA(acc[mf][nt], ah[cur][mf], bh[cur][nt]);
            #pragma unroll
            for (int mf = 0; mf < 2; mf++)
                #pragma unroll
                for (int nt = 0; nt < 4; nt++)
                    MMA(acc[mf][nt], ah[cur][mf], bl[cur][nt]);
            #pragma unroll
            for (int mf = 0; mf < 2; mf++)
                #pragma unroll
                for (int nt = 0; nt < 4; nt++)
                    MMA(acc[mf][nt], al[cur][mf], bh[cur][nt]);
        }
    };
    auto store_y = [&](uint32_t yh, uint32_t yl) {
        #pragma unroll
        for (int mf = 0; mf < 2; mf++)
            #pragma unroll
            for (int nt = 0; nt < 4; nt++) {
                int ch = nbase + nt * 8 + 2 * t4;
                int tok = mbase + mf * 16 + g;
                uint32_t hi, lo;
                split2(acc[mf][nt][0], acc[mf][nt][1], hi, lo);
                *(uint32_t*)(smem + yh + SWZ(tok, ch * 2)) = hi;
                *(uint32_t*)(smem + yl + SWZ(tok, ch * 2)) = lo;
                split2(acc[mf][nt][2], acc[mf][nt][3], hi, lo);
                *(uint32_t*)(smem + yh + SWZ(tok + 8, ch * 2)) = hi;
                *(uint32_t*)(smem + yl + SWZ(tok + 8, ch * 2)) = lo;
            }
    };

    // ---- q-gemm -> registers; then ARRIVE only (no wait) ----
    gemm(PW(0), PW(1));
    uint32_t qfh[2][2][4], qfl[2][2][4];
    #pragma unroll
    for (int mf = 0; mf < 2; mf++)
        #pragma unroll
        for (int kt = 0; kt < 2; kt++) {
            split2(acc[mf][2*kt][0] * SCALE_, acc[mf][2*kt][1] * SCALE_, qfh[mf][kt][0], qfl[mf][kt][0]);
            split2(acc[mf][2*kt][2] * SCALE_, acc[mf][2*kt][3] * SCALE_, qfh[mf][kt][1], qfl[mf][kt][1]);
            split2(acc[mf][2*kt+1][0] * SCALE_, acc[mf][2*kt+1][1] * SCALE_, qfh[mf][kt][2], qfl[mf][kt][2]);
            split2(acc[mf][2*kt+1][2] * SCALE_, acc[mf][2*kt+1][3] * SCALE_, qfh[mf][kt][3], qfl[mf][kt][3]);
        }
    BAR_ARRIVE();                         // credit: q-gemm done (P0/P1 reads complete)

    // ---- k-gemm immediately (independent planes); barrier closes after ----
    gemm(PW(2), PW(3));
    CP_WAITG(0);                          // all 6 W planes resident
    BAR_SYNC();                           // all warps past q AND k; W visible; P0-P3 write-safe
    store_y(KH2, KL2);                    // K -> spent q-weight planes

    // ---- v-gemm ----
    gemm(PW(4), PW(5));
    store_y(VH2, VL2);                    // V -> spent k-weight planes
    __syncthreads();                      // S3: K,V visible; P4/P5 free

    // proj weights prefetch under attention
    cpplane(PW(4), g_wp[0]);
    cpplane(PW(5), g_wp[1]);

    // ---- attention, per-mf to halve live registers ----
    {
        const int chB = (warp & 3) * 64;
        #pragma unroll
        for (int mf = 0; mf < 2; mf++) {
            float s[8][4];
            #pragma unroll
            for (int j = 0; j < 8; j++)
                #pragma unroll
                for (int q = 0; q < 4; q++) s[j][q] = 0.f;

            // QK^T pipelined
            {
                uint32_t kh[2][4], kl[2][4];
                auto loadK = [&](int it, int st) {
                    const int kt = it >> 2, ng = it & 3;
                    const int bcolb = chB + kt * 32 + ((lane >> 3) & 1) * 16;
                    const int brow = ng * 16 + ((lane >> 4) << 3) + (lane & 7);
                    LDSM4(kh[st][0], kh[st][1], kh[st][2], kh[st][3], sb + KH2 + SWZ(brow, bcolb));
                    LDSM4(kl[st][0], kl[st][1], kl[st][2], kl[st][3], sb + KL2 + SWZ(brow, bcolb));
                };
                loadK(0, 0);
                #pragma unroll
                for (int it = 0; it < 8; it++) {
                    const int cur = it & 1;
                    if (it < 7) loadK(it + 1, cur ^ 1);
                    const int kt = it >> 2, ng = it & 3;
                    MMA(s[2*ng],   qfh[mf][kt], kh[cur]);
                    MMA(s[2*ng+1], qfh[mf][kt], kh[cur] + 2);
                    MMA(s[2*ng],   qfh[mf][kt], kl[cur]);
                    MMA(s[2*ng+1], qfh[mf][kt], kl[cur] + 2);
                    MMA(s[2*ng],   qfl[mf][kt], kh[cur]);
                    MMA(s[2*ng+1], qfl[mf][kt], kh[cur] + 2);
                }
            }
            // softmax
            float mx0 = -1e30f, mx1 = -1e30f;
            #pragma unroll
            for (int j = 0; j < 8; j++) {
                mx0 = fmaxf(mx0, fmaxf(s[j][0], s[j][1]));
                mx1 = fmaxf(mx1, fmaxf(s[j][2], s[j][3]));
            }
            mx0 = fmaxf(mx0, __shfl_xor_sync(0xffffffffu, mx0, 1));
            mx0 = fmaxf(mx0, __shfl_xor_sync(0xffffffffu, mx0, 2));
            mx1 = fmaxf(mx1, __shfl_xor_sync(0xffffffffu, mx1, 1));
            mx1 = fmaxf(mx1, __shfl_xor_sync(0xffffffffu, mx1, 2));
            float sm0 = 0.f, sm1 = 0.f;
            #pragma unroll
            for (int j = 0; j < 8; j++) {
                s[j][0] = __expf(s[j][0] - mx0); sm0 += s[j][0];
                s[j][1] = __expf(s[j][1] - mx0); sm0 += s[j][1];
                s[j][2] = __expf(s[j][2] - mx1); sm1 += s[j][2];
                s[j][3] = __expf(s[j][3] - mx1); sm1 += s[j][3];
            }
            sm0 += __shfl_xor_sync(0xffffffffu, sm0, 1);
            sm0 += __shfl_xor_sync(0xffffffffu, sm0, 2);
            sm1 += __shfl_xor_sync(0xffffffffu, sm1, 1);
            sm1 += __shfl_xor_sync(0xffffffffu, sm1, 2);
            const float inv0 = 1.f / sm0, inv1 = 1.f / sm1;

            // P @ V pipelined
            float o[4][4];
            #pragma unroll
            for (int nt = 0; nt < 4; nt++)
                #pragma unroll
                for (int q = 0; q < 4; q++) o[nt][q] = 0.f;
            {
                uint32_t vh[2][4][2], vl[2][4][2];
                auto loadV = [&](int kt, int st) {
                    const int vrow = kt * 16 + (lane & 15);
                    #pragma unroll
                    for (int ng = 0; ng < 2; ng++) {
                        const int vcolb = chB + ng * 32 + (lane >> 4) * 16;
                        uint32_t r0, r1, r2, r3;
                        LDSM4T(r0, r1, r2, r3, sb + VH2 + SWZ(vrow, vcolb));
                        vh[st][2 * ng][0] = r0; vh[st][2 * ng][1] = r1;
                        vh[st][2 * ng + 1][0] = r2; vh[st][2 * ng + 1][1] = r3;
                        LDSM4T(r0, r1, r2, r3, sb + VL2 + SWZ(vrow, vcolb));
                        vl[st][2 * ng][0] = r0; vl[st][2 * ng][1] = r1;
                        vl[st][2 * ng + 1][0] = r2; vl[st][2 * ng + 1][1] = r3;
                    }
                };
                loadV(0, 0);
                #pragma unroll
                for (int kt = 0; kt < 4; kt++) {
                    const int cur = kt & 1;
                    if (kt < 3) loadV(kt + 1, cur ^ 1);
                    uint32_t pah[4], pal[4];
                    split2(s[2*kt][0] * inv0, s[2*kt][1] * inv0, pah[0], pal[0]);
                    split2(s[2*kt][2] * inv1, s[2*kt][3] * inv1, pah[1], pal[1]);
                    split2(s[2*kt+1][0] * inv0, s[2*kt+1][1] * inv0, pah[2], pal[2]);
                    split2(s[2*kt+1][2] * inv1, s[2*kt+1][3] * inv1, pah[3], pal[3]);
                    #pragma unroll
                    for (int nt = 0; nt < 4; nt++)
                        MMA(o[nt], pah, vh[cur][nt]);
                    #pragma unroll
                    for (int nt = 0; nt < 4; nt++)
                        MMA(o[nt], pah, vl[cur][nt]);
                    #pragma unroll
                    for (int nt = 0; nt < 4; nt++)
                        MMA(o[nt], pal, vh[cur][nt]);
                }
            }
            // store O (hi/lo) into X planes for this mf
            #pragma unroll
            for (int nt = 0; nt < 4; nt++) {
                int ch = (warp & 3) * 32 + nt * 8 + 2 * t4;
                int tok = (warp >> 2) * 32 + mf * 16 + g;
                uint32_t hi, lo;
                split2(o[nt][0], o[nt][1], hi, lo);
                *(uint32_t*)(smem + XHI + SWZ(tok, ch * 2)) = hi;
                *(uint32_t*)(smem + XLO + SWZ(tok, ch * 2)) = lo;
                split2(o[nt][2], o[nt][3], hi, lo);
                *(uint32_t*)(smem + XHI + SWZ(tok + 8, ch * 2)) = hi;
                *(uint32_t*)(smem + XLO + SWZ(tok + 8, ch * 2)) = lo;
            }
        }
    }
    CP_WAITG(0);          // proj planes resident
    __syncthreads();      // S4: O complete + Wproj visible

    // ---- proj = O @ Wproj + bias; direct global scatter ----
    gemm(PW(4), PW(5));
    {
        const float* bias = (const float*)(smem + BIASO);
        #pragma unroll
        for (int mf = 0; mf < 2; mf++) {
            const int tok0 = mbase + mf * 16 + g;
            const int tok1 = tok0 + 8;
            const int h0 = (hbase + (tok0 >> 3)) & 255, w0 = (wbase + (tok0 & 7)) & 255;
            const int h1 = (hbase + (tok1 >> 3)) & 255, w1 = (wbase + (tok1 & 7)) & 255;
            const size_t p0 = (size_t)h0 * 256 + w0;
            const size_t p1 = (size_t)h1 * 256 + w1;
            #pragma unroll
            for (int nt = 0; nt < 4; nt++) {
                const int c0 = nbase + nt * 8 + 2 * t4, c1 = c0 + 1;
                float* o0 = out + (size_t)(b * 128 + c0) * 65536;
                float* o1 = out + (size_t)(b * 128 + c1) * 65536;
                o0[p0] = acc[mf][nt][0] + bias[c0];
                o1[p0] = acc[mf][nt][1] + bias[c1];
                o0[p1] = acc[mf][nt][2] + bias[c0];
                o1[p1] = acc[mf][nt][3] + bias[c1];
            }
        }
    }
}

extern "C" void kernel_launch(void* const* d_in, const int* in_sizes, int n_in,
                              void* d_out, int out_size)
{
    const float* x      = (const float*)d_in[0];
    const float* w_qkv  = (const float*)d_in[1];
    const float* w_proj = (const float*)d_in[2];
    const float* b_proj = (const float*)d_in[3];
    float* out = (float*)d_out;

    prep_weights<<<256, 256>>>(w_qkv, w_proj);

    cudaFuncSetAttribute(swin_mma7_kernel,
                         cudaFuncAttributeMaxDynamicSharedMemorySize, SMEM_BYTES);
    swin_mma7_kernel<<<8192, 256, SMEM_BYTES>>>(x, b_proj, out);
}

// round 13
// speedup vs baseline: 1.0381x; 1.0357x over previous
#include <cuda_runtime.h>
#include <cuda_bf16.h>
#include <cstdint>

// SwinStyleAttention, mma.sync bf16 hi/lo 3-pass. R12: weights bypass smem entirely
// (pre-packed ldmatrix-order fragments read via LDG.128 from L2); smem 98.8KB ->
// 2 CTAs/SM for cross-CTA pipe overlap; 4 barriers. 1 CTA = 1 window, 8 warps.

#define SCALE_ 0.17677669529663687f
#define SWZ(row, colb) (((row) << 8) + ((colb) ^ (((row) & 7) << 4)))

#define XHI   0            // x hi plane (64x128 bf16) -> V hi after v-gemm
#define XLO   16384
#define KH    32768
#define KL    49152
#define OH    65536
#define OL    81920
#define BIASO 98304
#define SMEM_BYTES 98816

// Pre-packed B fragments in ldmatrix order:
// index = ((((c*2+part)*4 + wn)*8 + kt)*32 + lane)*8 + j,  c: 0=q,1=k,2=v,3=proj
__device__ uint32_t g_bfrag[4 * 2 * 4 * 8 * 32 * 8];

static __device__ __forceinline__ uint32_t smem_u32(const void* p) {
    uint32_t a;
    asm("{ .reg .u64 t; cvta.to.shared.u64 t, %1; cvt.u32.u64 %0, t; }" : "=r"(a) : "l"(p));
    return a;
}

#define LDSM4(R0, R1, R2, R3, ADDR) \
    asm volatile("ldmatrix.sync.aligned.m8n8.x4.shared.b16 {%0,%1,%2,%3}, [%4];" \
                 : "=r"(R0), "=r"(R1), "=r"(R2), "=r"(R3) : "r"(ADDR))
#define LDSM4T(R0, R1, R2, R3, ADDR) \
    asm volatile("ldmatrix.sync.aligned.m8n8.x4.trans.shared.b16 {%0,%1,%2,%3}, [%4];" \
                 : "=r"(R0), "=r"(R1), "=r"(R2), "=r"(R3) : "r"(ADDR))
#define MMA(D, A, B) \
    asm volatile("mma.sync.aligned.m16n8k16.row.col.f32.bf16.bf16.f32 " \
                 "{%0,%1,%2,%3},{%4,%5,%6,%7},{%8,%9},{%0,%1,%2,%3};" \
                 : "+f"((D)[0]), "+f"((D)[1]), "+f"((D)[2]), "+f"((D)[3]) \
                 : "r"((A)[0]), "r"((A)[1]), "r"((A)[2]), "r"((A)[3]), \
                   "r"((B)[0]), "r"((B)[1]))

static __device__ __forceinline__ void split2(float x, float y, uint32_t& hi, uint32_t& lo) {
    __nv_bfloat16 hx = __float2bfloat16(x), hy = __float2bfloat16(y);
    __nv_bfloat16 lx = __float2bfloat16(x - __bfloat162float(hx));
    __nv_bfloat16 ly = __float2bfloat16(y - __bfloat162float(hy));
    hi = (uint32_t)__bfloat16_as_ushort(hx) | ((uint32_t)__bfloat16_as_ushort(hy) << 16);
    lo = (uint32_t)__bfloat16_as_ushort(lx) | ((uint32_t)__bfloat16_as_ushort(ly) << 16);
}

// ---- prep: pack W hi/lo fragments exactly as ldmatrix would deliver them ----
// Replicates: reg m of lane l = 4 bytes at (row of lane 8m+(l>>2)) + 4*(l&3), where
// row(p) = wn*32 + ng*16 + ((p>>4)<<3) + (p&7), colb(p) = kt*32 + ((p>>3)&1)*16.
__global__ void prep_weights(const float* __restrict__ wqkv, const float* __restrict__ wproj) {
    int i = blockIdx.x * blockDim.x + threadIdx.x;      // 65536 entries
    int j    = i & 7;
    int lane = (i >> 3) & 31;
    int kt   = (i >> 8) & 7;
    int wn   = (i >> 11) & 3;
    int part = (i >> 13) & 1;
    int c    = i >> 14;                                  // 0=q,1=k,2=v,3=proj
    int ng = j >> 2, m = j & 3;
    int p = 8 * m + (lane >> 2);
    int n = wn * 32 + ng * 16 + ((p >> 4) << 3) + (p & 7);
    int kbyte = kt * 32 + ((p >> 3) & 1) * 16 + 4 * (lane & 3);
    int k0 = kbyte >> 1;
    float v0, v1;
    if (c < 3) { v0 = wqkv[k0 * 384 + c * 128 + n]; v1 = wqkv[(k0 + 1) * 384 + c * 128 + n]; }
    else       { v0 = wproj[k0 * 128 + n];          v1 = wproj[(k0 + 1) * 128 + n]; }
    __nv_bfloat16 h0 = __float2bfloat16(v0), h1 = __float2bfloat16(v1);
    uint32_t val;
    if (part == 0) {
        val = (uint32_t)__bfloat16_as_ushort(h0) | ((uint32_t)__bfloat16_as_ushort(h1) << 16);
    } else {
        __nv_bfloat16 l0 = __float2bfloat16(v0 - __bfloat162float(h0));
        __nv_bfloat16 l1 = __float2bfloat16(v1 - __bfloat162float(h1));
        val = (uint32_t)__bfloat16_as_ushort(l0) | ((uint32_t)__bfloat16_as_ushort(l1) << 16);
    }
    g_bfrag[i] = val;
}

// ---------------- main fused kernel: 2 CTAs/SM ----------------
__global__ __launch_bounds__(256, 2)
void swin_mma8_kernel(const float* __restrict__ x,
                      const float* __restrict__ b_proj,
                      float* __restrict__ out)
{
    extern __shared__ __align__(256) unsigned char smem[];
    const uint32_t sb = smem_u32(smem);

    const int tid = threadIdx.x;
    const int lane = tid & 31;
    const int warp = tid >> 5;     // 0..7
    const int g = lane >> 2;
    const int t4 = lane & 3;

    const int win = blockIdx.x;
    const int b = win >> 10, wy = (win >> 5) & 31, wx = win & 31;
    const int hbase = wy * 8 + 4, wbase = wx * 8 + 4;

    // ---- phase 0: bias + rolled-window gather into X hi/lo planes ----
    if (tid < 128) ((float*)(smem + BIASO))[tid] = b_proj[tid];
    #pragma unroll
    for (int it = 0; it < 4; it++) {
        int idx = tid + it * 256;
        int t = idx & 63, cq = idx >> 6;
        int h = (hbase + (t >> 3)) & 255;
        int w = (wbase + (t & 7)) & 255;
        const float* xg = x + (size_t)(b * 128 + cq * 8) * 65536 + h * 256 + w;
        uint32_t hp[4], lp[4];
        #pragma unroll
        for (int jj = 0; jj < 4; jj++) {
            float f0 = xg[(size_t)(2 * jj) << 16];
            float f1 = xg[(size_t)(2 * jj + 1) << 16];
            split2(f0, f1, hp[jj], lp[jj]);
        }
        *(uint4*)(smem + XHI + SWZ(t, cq * 16)) = make_uint4(hp[0], hp[1], hp[2], hp[3]);
        *(uint4*)(smem + XLO + SWZ(t, cq * 16)) = make_uint4(lp[0], lp[1], lp[2], lp[3]);
    }
    __syncthreads();               // S1: X visible

    const int mbase = (warp >> 2) * 32;
    const int nbase = (warp & 3) * 32;
    const int wn = warp & 3;

    float acc[2][4][4];
    // GEMM: A = smem planes (aHi, aHi+16384), B = global pre-packed fragments (chunk c)
    auto gemm = [&](uint32_t aHi, int c) {
        #pragma unroll
        for (int mf = 0; mf < 2; mf++)
            #pragma unroll
            for (int nt = 0; nt < 4; nt++)
                #pragma unroll
                for (int q = 0; q < 4; q++) acc[mf][nt][q] = 0.f;
        const int arow = mbase + (lane & 15);
        const uint4* bph = (const uint4*)g_bfrag + (size_t)(((c * 2 + 0) * 4 + wn) * 8) * 64 + lane * 2;
        const uint4* bpl = (const uint4*)g_bfrag + (size_t)(((c * 2 + 1) * 4 + wn) * 8) * 64 + lane * 2;
        uint32_t bh[2][4][2], bl[2][4][2];
        auto loadB = [&](int kt, int st) {
            uint4 h0 = bph[kt * 64], h1 = bph[kt * 64 + 1];
            uint4 l0 = bpl[kt * 64], l1 = bpl[kt * 64 + 1];
            bh[st][0][0] = h0.x; bh[st][0][1] = h0.y; bh[st][1][0] = h0.z; bh[st][1][1] = h0.w;
            bh[st][2][0] = h1.x; bh[st][2][1] = h1.y; bh[st][3][0] = h1.z; bh[st][3][1] = h1.w;
            bl[st][0][0] = l0.x; bl[st][0][1] = l0.y; bl[st][1][0] = l0.z; bl[st][1][1] = l0.w;
            bl[st][2][0] = l1.x; bl[st][2][1] = l1.y; bl[st][3][0] = l1.z; bl[st][3][1] = l1.w;
        };
        loadB(0, 0);
        #pragma unroll
        for (int kt = 0; kt < 8; kt++) {
            const int cur = kt & 1;
            if (kt < 7) loadB(kt + 1, cur ^ 1);
            uint32_t ah[2][4], al[2][4];
            const int acolb = kt * 32 + (lane >> 4) * 16;
            #pragma unroll
            for (int mf = 0; mf < 2; mf++) {
                LDSM4(ah[mf][0], ah[mf][1], ah[mf][2], ah[mf][3],
                      sb + aHi + SWZ(arow + mf * 16, acolb));
                LDSM4(al[mf][0], al[mf][1], al[mf][2], al[mf][3],
                      sb + aHi + 16384 + SWZ(arow + mf * 16, acolb));
            }
            #pragma unroll
            for (int mf = 0; mf < 2; mf++)
                #pragma unroll
                for (int nt = 0; nt < 4; nt++)
                    MMA(acc[mf][nt], ah[mf], bh[cur][nt]);
            #pragma unroll
            for (int mf = 0; mf < 2; mf++)
                #pragma unroll
                for (int nt = 0; nt < 4; nt++)
                    MMA(acc[mf][nt], ah[mf], bl[cur][nt]);
            #pragma unroll
            for (int mf = 0; mf < 2; mf++)
                #pragma unroll
                for (int nt = 0; nt < 4; nt++)
                    MMA(acc[mf][nt], al[mf], bh[cur][nt]);
        }
    };
    auto store_y = [&](uint32_t yh, uint32_t yl) {
        #pragma unroll
        for (int mf = 0; mf < 2; mf++)
            #pragma unroll
            for (int nt = 0; nt < 4; nt++) {
                int ch = nbase + nt * 8 + 2 * t4;
                int tok = mbase + mf * 16 + g;
                uint32_t hi, lo;
                split2(acc[mf][nt][0], acc[mf][nt][1], hi, lo);
                *(uint32_t*)(smem + yh + SWZ(tok, ch * 2)) = hi;
                *(uint32_t*)(smem + yl + SWZ(tok, ch * 2)) = lo;
                split2(acc[mf][nt][2], acc[mf][nt][3], hi, lo);
                *(uint32_t*)(smem + yh + SWZ(tok + 8, ch * 2)) = hi;
                *(uint32_t*)(smem + yl + SWZ(tok + 8, ch * 2)) = lo;
            }
    };

    // ---- k-gemm first (K store early, no reader conflicts) ----
    gemm(XHI, 1);
    store_y(KH, KL);

    // ---- q-gemm -> registers only (short qf live range) ----
    gemm(XHI, 0);
    uint32_t qfh[2][2][4], qfl[2][2][4];
    #pragma unroll
    for (int mf = 0; mf < 2; mf++)
        #pragma unroll
        for (int kt = 0; kt < 2; kt++) {
            split2(acc[mf][2*kt][0] * SCALE_, acc[mf][2*kt][1] * SCALE_, qfh[mf][kt][0], qfl[mf][kt][0]);
            split2(acc[mf][2*kt][2] * SCALE_, acc[mf][2*kt][3] * SCALE_, qfh[mf][kt][1], qfl[mf][kt][1]);
            split2(acc[mf][2*kt+1][0] * SCALE_, acc[mf][2*kt+1][1] * SCALE_, qfh[mf][kt][2], qfl[mf][kt][2]);
            split2(acc[mf][2*kt+1][2] * SCALE_, acc[mf][2*kt+1][3] * SCALE_, qfh[mf][kt][3], qfl[mf][kt][3]);
        }

    // ---- v-gemm ----
    gemm(XHI, 2);
    __syncthreads();               // S2: all X reads done; K stores visible
    store_y(XHI, XLO);             // V overwrites X planes
    __syncthreads();               // S3: V visible

    // ---- attention, per-mf; O -> OH/OL planes ----
    {
        const int chB = (warp & 3) * 64;
        #pragma unroll
        for (int mf = 0; mf < 2; mf++) {
            float s[8][4];
            #pragma unroll
            for (int j = 0; j < 8; j++)
                #pragma unroll
                for (int q = 0; q < 4; q++) s[j][q] = 0.f;

            {   // QK^T pipelined over smem K
                uint32_t kh[2][4], kl[2][4];
                auto loadK = [&](int it, int st) {
                    const int kt = it >> 2, ng = it & 3;
                    const int bcolb = chB + kt * 32 + ((lane >> 3) & 1) * 16;
                    const int brow = ng * 16 + ((lane >> 4) << 3) + (lane & 7);
                    LDSM4(kh[st][0], kh[st][1], kh[st][2], kh[st][3], sb + KH + SWZ(brow, bcolb));
                    LDSM4(kl[st][0], kl[st][1], kl[st][2], kl[st][3], sb + KL + SWZ(brow, bcolb));
                };
                loadK(0, 0);
                #pragma unroll
                for (int it = 0; it < 8; it++) {
                    const int cur = it & 1;
                    if (it < 7) loadK(it + 1, cur ^ 1);
                    const int kt = it >> 2, ng = it & 3;
                    MMA(s[2*ng],   qfh[mf][kt], kh[cur]);
                    MMA(s[2*ng+1], qfh[mf][kt], kh[cur] + 2);
                    MMA(s[2*ng],   qfh[mf][kt], kl[cur]);
                    MMA(s[2*ng+1], qfh[mf][kt], kl[cur] + 2);
                    MMA(s[2*ng],   qfl[mf][kt], kh[cur]);
                    MMA(s[2*ng+1], qfl[mf][kt], kh[cur] + 2);
                }
            }
            // softmax
            float mx0 = -1e30f, mx1 = -1e30f;
            #pragma unroll
            for (int j = 0; j < 8; j++) {
                mx0 = fmaxf(mx0, fmaxf(s[j][0], s[j][1]));
                mx1 = fmaxf(mx1, fmaxf(s[j][2], s[j][3]));
            }
            mx0 = fmaxf(mx0, __shfl_xor_sync(0xffffffffu, mx0, 1));
            mx0 = fmaxf(mx0, __shfl_xor_sync(0xffffffffu, mx0, 2));
            mx1 = fmaxf(mx1, __shfl_xor_sync(0xffffffffu, mx1, 1));
            mx1 = fmaxf(mx1, __shfl_xor_sync(0xffffffffu, mx1, 2));
            float sm0 = 0.f, sm1 = 0.f;
            #pragma unroll
            for (int j = 0; j < 8; j++) {
                s[j][0] = __expf(s[j][0] - mx0); sm0 += s[j][0];
                s[j][1] = __expf(s[j][1] - mx0); sm0 += s[j][1];
                s[j][2] = __expf(s[j][2] - mx1); sm1 += s[j][2];
                s[j][3] = __expf(s[j][3] - mx1); sm1 += s[j][3];
            }
            sm0 += __shfl_xor_sync(0xffffffffu, sm0, 1);
            sm0 += __shfl_xor_sync(0xffffffffu, sm0, 2);
            sm1 += __shfl_xor_sync(0xffffffffu, sm1, 1);
            sm1 += __shfl_xor_sync(0xffffffffu, sm1, 2);
            const float inv0 = 1.f / sm0, inv1 = 1.f / sm1;

            // P @ V (V lives in X planes)
            float o[4][4];
            #pragma unroll
            for (int nt = 0; nt < 4; nt++)
                #pragma unroll
                for (int q = 0; q < 4; q++) o[nt][q] = 0.f;
            {
                uint32_t vh[2][4][2], vl[2][4][2];
                auto loadV = [&](int kt, int st) {
                    const int vrow = kt * 16 + (lane & 15);
                    #pragma unroll
                    for (int ng = 0; ng < 2; ng++) {
                        const int vcolb = chB + ng * 32 + (lane >> 4) * 16;
                        uint32_t r0, r1, r2, r3;
                        LDSM4T(r0, r1, r2, r3, sb + XHI + SWZ(vrow, vcolb));
                        vh[st][2 * ng][0] = r0; vh[st][2 * ng][1] = r1;
                        vh[st][2 * ng + 1][0] = r2; vh[st][2 * ng + 1][1] = r3;
                        LDSM4T(r0, r1, r2, r3, sb + XLO + SWZ(vrow, vcolb));
                        vl[st][2 * ng][0] = r0; vl[st][2 * ng][1] = r1;
                        vl[st][2 * ng + 1][0] = r2; vl[st][2 * ng + 1][1] = r3;
                    }
                };
                loadV(0, 0);
                #pragma unroll
                for (int kt = 0; kt < 4; kt++) {
                    const int cur = kt & 1;
                    if (kt < 3) loadV(kt + 1, cur ^ 1);
                    uint32_t pah[4], pal[4];
                    split2(s[2*kt][0] * inv0, s[2*kt][1] * inv0, pah[0], pal[0]);
                    split2(s[2*kt][2] * inv1, s[2*kt][3] * inv1, pah[1], pal[1]);
                    split2(s[2*kt+1][0] * inv0, s[2*kt+1][1] * inv0, pah[2], pal[2]);
                    split2(s[2*kt+1][2] * inv1, s[2*kt+1][3] * inv1, pah[3], pal[3]);
                    #pragma unroll
                    for (int nt = 0; nt < 4; nt++)
                        MMA(o[nt], pah, vh[cur][nt]);
                    #pragma unroll
                    for (int nt = 0; nt < 4; nt++)
                        MMA(o[nt], pah, vl[cur][nt]);
                    #pragma unroll
                    for (int nt = 0; nt < 4; nt++)
                        MMA(o[nt], pal, vh[cur][nt]);
                }
            }
            // store O (hi/lo) into O planes
            #pragma unroll
            for (int nt = 0; nt < 4; nt++) {
                int ch = (warp & 3) * 32 + nt * 8 + 2 * t4;
                int tok = (warp >> 2) * 32 + mf * 16 + g;
                uint32_t hi, lo;
                split2(o[nt][0], o[nt][1], hi, lo);
                *(uint32_t*)(smem + OH + SWZ(tok, ch * 2)) = hi;
                *(uint32_t*)(smem + OL + SWZ(tok, ch * 2)) = lo;
                split2(o[nt][2], o[nt][3], hi, lo);
                *(uint32_t*)(smem + OH + SWZ(tok + 8, ch * 2)) = hi;
                *(uint32_t*)(smem + OL + SWZ(tok + 8, ch * 2)) = lo;
            }
        }
    }
    __syncthreads();               // S4: O visible

    // ---- proj = O @ Wproj + bias; direct global scatter ----
    gemm(OH, 3);
    {
        const float* bias = (const float*)(smem + BIASO);
        #pragma unroll
        for (int mf = 0; mf < 2; mf++) {
            const int tok0 = mbase + mf * 16 + g;
            const int tok1 = tok0 + 8;
            const int h0 = (hbase + (tok0 >> 3)) & 255, w0 = (wbase + (tok0 & 7)) & 255;
            const int h1 = (hbase + (tok1 >> 3)) & 255, w1 = (wbase + (tok1 & 7)) & 255;
            const size_t p0 = (size_t)h0 * 256 + w0;
            const size_t p1 = (size_t)h1 * 256 + w1;
            #pragma unroll
            for (int nt = 0; nt < 4; nt++) {
                const int c0 = nbase + nt * 8 + 2 * t4, c1 = c0 + 1;
                float* o0 = out + (size_t)(b * 128 + c0) * 65536;
                float* o1 = out + (size_t)(b * 128 + c1) * 65536;
                o0[p0] = acc[mf][nt][0] + bias[c0];
                o1[p0] = acc[mf][nt][1] + bias[c1];
                o0[p1] = acc[mf][nt][2] + bias[c0];
                o1[p1] = acc[mf][nt][3] + bias[c1];
            }
        }
    }
}

extern "C" void kernel_launch(void* const* d_in, const int* in_sizes, int n_in,
                              void* d_out, int out_size)
{
    const float* x      = (const float*)d_in[0];
    const float* w_qkv  = (const float*)d_in[1];
    const float* w_proj = (const float*)d_in[2];
    const float* b_proj = (const float*)d_in[3];
    float* out = (float*)d_out;

    prep_weights<<<256, 256>>>(w_qkv, w_proj);

    cudaFuncSetAttribute(swin_mma8_kernel,
                         cudaFuncAttributeMaxDynamicSharedMemorySize, SMEM_BYTES);
    swin_mma8_kernel<<<8192, 256, SMEM_BYTES>>>(x, b_proj, out);
}

// round 14
// speedup vs baseline: 2.5719x; 2.4776x over previous
#include <cuda_runtime.h>
#include <cuda_fp16.h>
#include <cstdint>

// SwinStyleAttention. R14: fp16 SINGLE-PASS mma (fp16 has 11 mantissa bits;
// error budget 1e-3 permits it). MMAs /3, operand bytes /2 vs R12's bf16 3-pass.
// Weights as pre-packed ldmatrix-order fragments via LDG (no smem). 2 CTAs/SM.

#define SCALE_ 0.17677669529663687f
#define SWZ(row, colb) (((row) << 8) + ((colb) ^ (((row) & 7) << 4)))

#define XH    0            // x plane (64 rows x 128 fp16) -> V plane after v-gemm
#define KHP   16384
#define OHP   32768
#define BIASO 49152
#define SMEM_BYTES 49664

// Pre-packed B fragments in ldmatrix order (fp16, single precision level):
// index = (((c*4 + wn)*8 + kt)*32 + lane)*8 + j,  c: 0=q,1=k,2=v,3=proj
__device__ uint32_t g_bfrag[4 * 4 * 8 * 32 * 8];

static __device__ __forceinline__ uint32_t smem_u32(const void* p) {
    uint32_t a;
    asm("{ .reg .u64 t; cvta.to.shared.u64 t, %1; cvt.u32.u64 %0, t; }" : "=r"(a) : "l"(p));
    return a;
}
static __device__ __forceinline__ uint32_t pack2(float x, float y) {
    __half2 h = __floats2half2_rn(x, y);
    return *(uint32_t*)&h;
}

#define LDSM4(R0, R1, R2, R3, ADDR) \
    asm volatile("ldmatrix.sync.aligned.m8n8.x4.shared.b16 {%0,%1,%2,%3}, [%4];" \
                 : "=r"(R0), "=r"(R1), "=r"(R2), "=r"(R3) : "r"(ADDR))
#define LDSM4T(R0, R1, R2, R3, ADDR) \
    asm volatile("ldmatrix.sync.aligned.m8n8.x4.trans.shared.b16 {%0,%1,%2,%3}, [%4];" \
                 : "=r"(R0), "=r"(R1), "=r"(R2), "=r"(R3) : "r"(ADDR))
#define MMA(D, A, B) \
    asm volatile("mma.sync.aligned.m16n8k16.row.col.f32.f16.f16.f32 " \
                 "{%0,%1,%2,%3},{%4,%5,%6,%7},{%8,%9},{%0,%1,%2,%3};" \
                 : "+f"((D)[0]), "+f"((D)[1]), "+f"((D)[2]), "+f"((D)[3]) \
                 : "r"((A)[0]), "r"((A)[1]), "r"((A)[2]), "r"((A)[3]), \
                   "r"((B)[0]), "r"((B)[1]))

// ---- prep: pack W fragments exactly as ldmatrix would deliver them (fp16) ----
__global__ void prep_weights(const float* __restrict__ wqkv, const float* __restrict__ wproj) {
    int i = blockIdx.x * blockDim.x + threadIdx.x;      // 32768 entries
    if (i >= 32768) return;
    int j    = i & 7;
    int lane = (i >> 3) & 31;
    int kt   = (i >> 8) & 7;
    int wn   = (i >> 11) & 3;
    int c    = i >> 13;                                  // 0=q,1=k,2=v,3=proj
    int ng = j >> 2, m = j & 3;
    int p = 8 * m + (lane >> 2);
    int n = wn * 32 + ng * 16 + ((p >> 4) << 3) + (p & 7);
    int kbyte = kt * 32 + ((p >> 3) & 1) * 16 + 4 * (lane & 3);
    int k0 = kbyte >> 1;
    float v0, v1;
    if (c < 3) { v0 = wqkv[k0 * 384 + c * 128 + n]; v1 = wqkv[(k0 + 1) * 384 + c * 128 + n]; }
    else       { v0 = wproj[k0 * 128 + n];          v1 = wproj[(k0 + 1) * 128 + n]; }
    g_bfrag[i] = pack2(v0, v1);
}

// ---------------- main fused kernel: 2 CTAs/SM ----------------
__global__ __launch_bounds__(256, 2)
void swin_mma9_kernel(const float* __restrict__ x,
                      const float* __restrict__ b_proj,
                      float* __restrict__ out)
{
    extern __shared__ __align__(256) unsigned char smem[];
    const uint32_t sb = smem_u32(smem);

    const int tid = threadIdx.x;
    const int lane = tid & 31;
    const int warp = tid >> 5;     // 0..7
    const int g = lane >> 2;
    const int t4 = lane & 3;

    const int win = blockIdx.x;
    const int b = win >> 10, wy = (win >> 5) & 31, wx = win & 31;
    const int hbase = wy * 8 + 4, wbase = wx * 8 + 4;

    // ---- phase 0: bias + rolled-window gather into X plane (fp16) ----
    if (tid < 128) ((float*)(smem + BIASO))[tid] = b_proj[tid];
    #pragma unroll
    for (int it = 0; it < 4; it++) {
        int idx = tid + it * 256;
        int t = idx & 63, cq = idx >> 6;
        int h = (hbase + (t >> 3)) & 255;
        int w = (wbase + (t & 7)) & 255;
        const float* xg = x + (size_t)(b * 128 + cq * 8) * 65536 + h * 256 + w;
        uint32_t hp[4];
        #pragma unroll
        for (int jj = 0; jj < 4; jj++) {
            float f0 = xg[(size_t)(2 * jj) << 16];
            float f1 = xg[(size_t)(2 * jj + 1) << 16];
            hp[jj] = pack2(f0, f1);
        }
        *(uint4*)(smem + XH + SWZ(t, cq * 16)) = make_uint4(hp[0], hp[1], hp[2], hp[3]);
    }
    __syncthreads();               // S1: X visible

    const int mbase = (warp >> 2) * 32;
    const int nbase = (warp & 3) * 32;
    const int wn = warp & 3;

    float acc[2][4][4];
    // single-pass GEMM: A = smem plane, B = global pre-packed fragments (chunk c)
    auto gemm = [&](uint32_t aPl, int c) {
        #pragma unroll
        for (int mf = 0; mf < 2; mf++)
            #pragma unroll
            for (int nt = 0; nt < 4; nt++)
                #pragma unroll
                for (int q = 0; q < 4; q++) acc[mf][nt][q] = 0.f;
        const int arow = mbase + (lane & 15);
        const uint4* bp = (const uint4*)g_bfrag + (size_t)((c * 4 + wn) * 8) * 64 + lane * 2;
        uint32_t bfr[2][4][2];
        auto loadB = [&](int kt, int st) {
            uint4 h0 = bp[kt * 64], h1 = bp[kt * 64 + 1];
            bfr[st][0][0] = h0.x; bfr[st][0][1] = h0.y; bfr[st][1][0] = h0.z; bfr[st][1][1] = h0.w;
            bfr[st][2][0] = h1.x; bfr[st][2][1] = h1.y; bfr[st][3][0] = h1.z; bfr[st][3][1] = h1.w;
        };
        loadB(0, 0);
        #pragma unroll
        for (int kt = 0; kt < 8; kt++) {
            const int cur = kt & 1;
            if (kt < 7) loadB(kt + 1, cur ^ 1);
            uint32_t ah[2][4];
            const int acolb = kt * 32 + (lane >> 4) * 16;
            #pragma unroll
            for (int mf = 0; mf < 2; mf++)
                LDSM4(ah[mf][0], ah[mf][1], ah[mf][2], ah[mf][3],
                      sb + aPl + SWZ(arow + mf * 16, acolb));
            #pragma unroll
            for (int mf = 0; mf < 2; mf++)
                #pragma unroll
                for (int nt = 0; nt < 4; nt++)
                    MMA(acc[mf][nt], ah[mf], bfr[cur][nt]);
        }
    };
    auto store_y = [&](uint32_t yPl) {
        #pragma unroll
        for (int mf = 0; mf < 2; mf++)
            #pragma unroll
            for (int nt = 0; nt < 4; nt++) {
                int ch = nbase + nt * 8 + 2 * t4;
                int tok = mbase + mf * 16 + g;
                *(uint32_t*)(smem + yPl + SWZ(tok, ch * 2)) =
                    pack2(acc[mf][nt][0], acc[mf][nt][1]);
                *(uint32_t*)(smem + yPl + SWZ(tok + 8, ch * 2)) =
                    pack2(acc[mf][nt][2], acc[mf][nt][3]);
            }
    };

    // ---- k-gemm first (store early), then q-gemm (regs), then v-gemm ----
    gemm(XH, 1);
    store_y(KHP);

    gemm(XH, 0);
    uint32_t qf[2][2][4];          // [mf][kt16][frag], SCALE folded
    #pragma unroll
    for (int mf = 0; mf < 2; mf++)
        #pragma unroll
        for (int kt = 0; kt < 2; kt++) {
            qf[mf][kt][0] = pack2(acc[mf][2*kt][0] * SCALE_,   acc[mf][2*kt][1] * SCALE_);
            qf[mf][kt][1] = pack2(acc[mf][2*kt][2] * SCALE_,   acc[mf][2*kt][3] * SCALE_);
            qf[mf][kt][2] = pack2(acc[mf][2*kt+1][0] * SCALE_, acc[mf][2*kt+1][1] * SCALE_);
            qf[mf][kt][3] = pack2(acc[mf][2*kt+1][2] * SCALE_, acc[mf][2*kt+1][3] * SCALE_);
        }

    gemm(XH, 2);
    __syncthreads();               // S2: all X reads done; K visible
    store_y(XH);                   // V overwrites X plane
    __syncthreads();               // S3: V visible

    // ---- attention, per-mf; O -> O plane ----
    {
        const int chB = (warp & 3) * 64;
        #pragma unroll
        for (int mf = 0; mf < 2; mf++) {
            float s[8][4];
            #pragma unroll
            for (int j = 0; j < 8; j++)
                #pragma unroll
                for (int q = 0; q < 4; q++) s[j][q] = 0.f;

            {   // QK^T pipelined over smem K
                uint32_t kh[2][4];
                auto loadK = [&](int it, int st) {
                    const int kt = it >> 2, ng = it & 3;
                    const int bcolb = chB + kt * 32 + ((lane >> 3) & 1) * 16;
                    const int brow = ng * 16 + ((lane >> 4) << 3) + (lane & 7);
                    LDSM4(kh[st][0], kh[st][1], kh[st][2], kh[st][3], sb + KHP + SWZ(brow, bcolb));
                };
                loadK(0, 0);
                #pragma unroll
                for (int it = 0; it < 8; it++) {
                    const int cur = it & 1;
                    if (it < 7) loadK(it + 1, cur ^ 1);
                    const int kt = it >> 2, ng = it & 3;
                    MMA(s[2*ng],   qf[mf][kt], kh[cur]);
                    MMA(s[2*ng+1], qf[mf][kt], kh[cur] + 2);
                }
            }
            // softmax (scale already folded into q)
            float mx0 = -1e30f, mx1 = -1e30f;
            #pragma unroll
            for (int j = 0; j < 8; j++) {
                mx0 = fmaxf(mx0, fmaxf(s[j][0], s[j][1]));
                mx1 = fmaxf(mx1, fmaxf(s[j][2], s[j][3]));
            }
            mx0 = fmaxf(mx0, __shfl_xor_sync(0xffffffffu, mx0, 1));
            mx0 = fmaxf(mx0, __shfl_xor_sync(0xffffffffu, mx0, 2));
            mx1 = fmaxf(mx1, __shfl_xor_sync(0xffffffffu, mx1, 1));
            mx1 = fmaxf(mx1, __shfl_xor_sync(0xffffffffu, mx1, 2));
            float sm0 = 0.f, sm1 = 0.f;
            #pragma unroll
            for (int j = 0; j < 8; j++) {
                s[j][0] = __expf(s[j][0] - mx0); sm0 += s[j][0];
                s[j][1] = __expf(s[j][1] - mx0); sm0 += s[j][1];
                s[j][2] = __expf(s[j][2] - mx1); sm1 += s[j][2];
                s[j][3] = __expf(s[j][3] - mx1); sm1 += s[j][3];
            }
            sm0 += __shfl_xor_sync(0xffffffffu, sm0, 1);
            sm0 += __shfl_xor_sync(0xffffffffu, sm0, 2);
            sm1 += __shfl_xor_sync(0xffffffffu, sm1, 1);
            sm1 += __shfl_xor_sync(0xffffffffu, sm1, 2);
            const float inv0 = 1.f / sm0, inv1 = 1.f / sm1;

            // P @ V (V lives in X plane)
            float o[4][4];
            #pragma unroll
            for (int nt = 0; nt < 4; nt++)
                #pragma unroll
                for (int q = 0; q < 4; q++) o[nt][q] = 0.f;
            {
                uint32_t vf[2][4][2];
                auto loadV = [&](int kt, int st) {
                    const int vrow = kt * 16 + (lane & 15);
                    #pragma unroll
                    for (int ng = 0; ng < 2; ng++) {
                        const int vcolb = chB + ng * 32 + (lane >> 4) * 16;
                        uint32_t r0, r1, r2, r3;
                        LDSM4T(r0, r1, r2, r3, sb + XH + SWZ(vrow, vcolb));
                        vf[st][2 * ng][0] = r0; vf[st][2 * ng][1] = r1;
                        vf[st][2 * ng + 1][0] = r2; vf[st][2 * ng + 1][1] = r3;
                    }
                };
                loadV(0, 0);
                #pragma unroll
                for (int kt = 0; kt < 4; kt++) {
                    const int cur = kt & 1;
                    if (kt < 3) loadV(kt + 1, cur ^ 1);
                    uint32_t pa[4];
                    pa[0] = pack2(s[2*kt][0] * inv0,   s[2*kt][1] * inv0);
                    pa[1] = pack2(s[2*kt][2] * inv1,   s[2*kt][3] * inv1);
                    pa[2] = pack2(s[2*kt+1][0] * inv0, s[2*kt+1][1] * inv0);
                    pa[3] = pack2(s[2*kt+1][2] * inv1, s[2*kt+1][3] * inv1);
                    #pragma unroll
                    for (int nt = 0; nt < 4; nt++)
                        MMA(o[nt], pa, vf[cur][nt]);
                }
            }
            // store O into O plane
            #pragma unroll
            for (int nt = 0; nt < 4; nt++) {
                int ch = (warp & 3) * 32 + nt * 8 + 2 * t4;
                int tok = (warp >> 2) * 32 + mf * 16 + g;
                *(uint32_t*)(smem + OHP + SWZ(tok, ch * 2)) = pack2(o[nt][0], o[nt][1]);
                *(uint32_t*)(smem + OHP + SWZ(tok + 8, ch * 2)) = pack2(o[nt][2], o[nt][3]);
            }
        }
    }
    __syncthreads();               // S4: O visible

    // ---- proj = O @ Wproj + bias; direct global scatter ----
    gemm(OHP, 3);
    {
        const float* bias = (const float*)(smem + BIASO);
        #pragma unroll
        for (int mf = 0; mf < 2; mf++) {
            const int tok0 = mbase + mf * 16 + g;
            const int tok1 = tok0 + 8;
            const int h0 = (hbase + (tok0 >> 3)) & 255, w0 = (wbase + (tok0 & 7)) & 255;
            const int h1 = (hbase + (tok1 >> 3)) & 255, w1 = (wbase + (tok1 & 7)) & 255;
            const size_t p0 = (size_t)h0 * 256 + w0;
            const size_t p1 = (size_t)h1 * 256 + w1;
            #pragma unroll
            for (int nt = 0; nt < 4; nt++) {
                const int c0 = nbase + nt * 8 + 2 * t4, c1 = c0 + 1;
                float* o0 = out + (size_t)(b * 128 + c0) * 65536;
                float* o1 = out + (size_t)(b * 128 + c1) * 65536;
                o0[p0] = acc[mf][nt][0] + bias[c0];
                o1[p0] = acc[mf][nt][1] + bias[c1];
                o0[p1] = acc[mf][nt][2] + bias[c0];
                o1[p1] = acc[mf][nt][3] + bias[c1];
            }
        }
    }
}

extern "C" void kernel_launch(void* const* d_in, const int* in_sizes, int n_in,
                              void* d_out, int out_size)
{
    const float* x      = (const float*)d_in[0];
    const float* w_qkv  = (const float*)d_in[1];
    const float* w_proj = (const float*)d_in[2];
    const float* b_proj = (const float*)d_in[3];
    float* out = (float*)d_out;

    prep_weights<<<128, 256>>>(w_qkv, w_proj);

    cudaFuncSetAttribute(swin_mma9_kernel,
                         cudaFuncAttributeMaxDynamicSharedMemorySize, SMEM_BYTES);
    swin_mma9_kernel<<<8192, 256, SMEM_BYTES>>>(x, b_proj, out);
}